// round 9
// baseline (speedup 1.0000x reference)
#include <cuda_runtime.h>
#include <math.h>

#define N_NODES 50000
#define D 256
#define D4 1024
#define NQ 128
#define PG 256
#define E1C 32768
#define E0C 32768
#define ME 64
#define SPAD 132
#define SP2 132

// ---------------- scratch (static device globals; referenced ONLY from device code) ----------------
__device__ __align__(16) float g_M[D4 * D4];   // Wq^T Wk
__device__ __align__(16) float g_v[NQ * D];
__device__ __align__(16) float g_wz[NQ * D];
__device__ __align__(16) float g_u[NQ * D];
__device__ float g_c[NQ];
__device__ __align__(16) float g_T1[N_NODES * D];
__device__ __align__(16) float g_T2[N_NODES * D];
__device__ __align__(16) float g_R1[E1C * D];
__device__ __align__(16) float g_R2[E1C * D];
__device__ float g_logits[E1C];
__device__ float g_exp[E1C];
__device__ float g_soft[E1C];
__device__ float g_target[E1C];
__device__ unsigned g_segmax[N_NODES];
__device__ float g_segsum[N_NODES];
__device__ int g_flag[N_NODES];
__device__ __align__(16) float g_NR1[N_NODES * D];
__device__ __align__(16) float g_NR2[N_NODES * D];
__device__ int g_s1[E1C], g_d1[E1C], g_q1[E1C];
__device__ int g_s0[E0C], g_d0[E0C], g_q0[E0C];
__device__ int g_psrc[NQ * ME], g_pdst[NQ * ME];
__device__ float g_psoft[NQ * ME], g_ptgt[NQ * ME];

#define BUF_T1 1
#define BUF_T2 2
#define BUF_R1 3
#define BUF_R2 4
#define BUF_NR1 5
#define BUF_NR2 6

__device__ __forceinline__ float* dbuf(int id) {
    switch (id) {
        case BUF_T1: return g_T1;
        case BUF_T2: return g_T2;
        case BUF_R1: return g_R1;
        case BUF_R2: return g_R2;
        case BUF_NR1: return g_NR1;
        default: return g_NR2;
    }
}

__device__ __forceinline__ unsigned fenc(float f) {
    unsigned u = __float_as_uint(f);
    return (u & 0x80000000u) ? ~u : (u | 0x80000000u);
}
__device__ __forceinline__ float fdec(unsigned e) {
    return __uint_as_float((e & 0x80000000u) ? (e ^ 0x80000000u) : ~e);
}

__device__ __forceinline__ unsigned f2tf32(float x) {
    unsigned r;
    asm("cvt.rna.tf32.f32 %0, %1;" : "=r"(r) : "f"(x));
    return r;
}

__device__ __forceinline__ void mma_tf32(float* c, unsigned a0, unsigned a1, unsigned a2,
                                         unsigned a3, unsigned b0, unsigned b1) {
    asm volatile(
        "mma.sync.aligned.m16n8k8.row.col.f32.tf32.tf32.f32 "
        "{%0,%1,%2,%3}, {%4,%5,%6,%7}, {%8,%9}, {%0,%1,%2,%3};"
        : "+f"(c[0]), "+f"(c[1]), "+f"(c[2]), "+f"(c[3])
        : "r"(a0), "r"(a1), "r"(a2), "r"(a3), "r"(b0), "r"(b1));
}

// hi/lo tf32 pair packed as float2 (x=hi bits, y=lo bits)
__device__ __forceinline__ float2 splitpack(float v) {
    unsigned h = f2tf32(v);
    unsigned l = f2tf32(v - __uint_as_float(h));
    return make_float2(__uint_as_float(h), __uint_as_float(l));
}

// ---------------- tensor-core split-tf32 GEMM ----------------
// C[R x N] = act( X[R x 256] @ W[N x 256]^T + bias ), fp32-accurate via hi/lo tf32 split.
// 128x128 block tile, 8 warps (2 m x 4 n of 64x32 warp tiles), 2 CTAs/SM.
// smem layout: [k][row] of float2(hi,lo) -> one LDS.64 per fragment element pair.
__global__ __launch_bounds__(256, 2) void k_gemm128t(
    const float* __restrict__ xext, int xid, int R,
    const float* __restrict__ wext, long woff, int ldwext,
    const float* __restrict__ bias, int act,
    float* __restrict__ c1ext, int c1id, int c2id)
{
    const float* X = xid ? dbuf(xid) : xext;
    const float* W = (woff >= 0) ? (g_M + woff) : wext;
    const int ldw = (woff >= 0) ? D4 : ldwext;

    __shared__ float2 Xs[16][SP2];
    __shared__ float2 Wsh[16][SP2];

    const int r0 = blockIdx.x * 128;
    const int j0 = blockIdx.y * 128;
    float* Cbase;
    if (c1id == 0 && c2id == 0) Cbase = c1ext + j0;
    else Cbase = (j0 < 256) ? (dbuf(c1id) + j0) : (dbuf(c2id) + (j0 - 256));

    const int tid = threadIdx.x;
    const int wid = tid >> 5;
    const int lane = tid & 31;
    const int m0 = (wid >> 2) * 64;
    const int n0 = (wid & 3) * 32;
    const int g = lane >> 2;
    const int t4 = lane & 3;

    float c[4][4][4];
#pragma unroll
    for (int mi = 0; mi < 4; mi++)
#pragma unroll
        for (int nj = 0; nj < 4; nj++)
#pragma unroll
            for (int k = 0; k < 4; k++) c[mi][nj][k] = 0.f;

    float4 xv[2], wv[2];

    // prime k-block 0
#pragma unroll
    for (int i = 0; i < 2; i++) {
        int f = tid + i * 256;
        int row = f >> 2, kq = (f & 3) << 2;
        float4 v = make_float4(0.f, 0.f, 0.f, 0.f);
        if (r0 + row < R) v = *(const float4*)(X + (size_t)(r0 + row) * D + kq);
        float4 w = *(const float4*)(W + (size_t)(j0 + row) * ldw + kq);
        Xs[kq + 0][row] = splitpack(v.x); Xs[kq + 1][row] = splitpack(v.y);
        Xs[kq + 2][row] = splitpack(v.z); Xs[kq + 3][row] = splitpack(v.w);
        Wsh[kq + 0][row] = splitpack(w.x); Wsh[kq + 1][row] = splitpack(w.y);
        Wsh[kq + 2][row] = splitpack(w.z); Wsh[kq + 3][row] = splitpack(w.w);
    }
    __syncthreads();

    for (int kb = 0; kb < 16; kb++) {
        if (kb < 15) {
            int k0 = (kb + 1) * 16;
#pragma unroll
            for (int i = 0; i < 2; i++) {
                int f = tid + i * 256;
                int row = f >> 2, kq = (f & 3) << 2;
                xv[i] = make_float4(0.f, 0.f, 0.f, 0.f);
                if (r0 + row < R) xv[i] = *(const float4*)(X + (size_t)(r0 + row) * D + k0 + kq);
                wv[i] = *(const float4*)(W + (size_t)(j0 + row) * ldw + k0 + kq);
            }
        }
#pragma unroll
        for (int ks = 0; ks < 16; ks += 8) {
            // B fragments for all 4 nj (packed hi/lo)
            float2 b0[4], b1[4];
#pragma unroll
            for (int nj = 0; nj < 4; nj++) {
                int nc = n0 + nj * 8 + g;
                b0[nj] = Wsh[ks + t4][nc];
                b1[nj] = Wsh[ks + 4 + t4][nc];
            }
#pragma unroll
            for (int mi = 0; mi < 4; mi++) {
                int mr = m0 + mi * 16;
                float2 a0 = Xs[ks + t4][mr + g];
                float2 a1 = Xs[ks + t4][mr + 8 + g];
                float2 a2 = Xs[ks + 4 + t4][mr + g];
                float2 a3 = Xs[ks + 4 + t4][mr + 8 + g];
                unsigned ah0 = __float_as_uint(a0.x), al0 = __float_as_uint(a0.y);
                unsigned ah1 = __float_as_uint(a1.x), al1 = __float_as_uint(a1.y);
                unsigned ah2 = __float_as_uint(a2.x), al2 = __float_as_uint(a2.y);
                unsigned ah3 = __float_as_uint(a3.x), al3 = __float_as_uint(a3.y);
#pragma unroll
                for (int nj = 0; nj < 4; nj++) {
                    unsigned bh0 = __float_as_uint(b0[nj].x), bl0 = __float_as_uint(b0[nj].y);
                    unsigned bh1 = __float_as_uint(b1[nj].x), bl1 = __float_as_uint(b1[nj].y);
                    mma_tf32(c[mi][nj], al0, al1, al2, al3, bh0, bh1);
                    mma_tf32(c[mi][nj], ah0, ah1, ah2, ah3, bl0, bl1);
                    mma_tf32(c[mi][nj], ah0, ah1, ah2, ah3, bh0, bh1);
                }
            }
        }
        __syncthreads();
        if (kb < 15) {
#pragma unroll
            for (int i = 0; i < 2; i++) {
                int f = tid + i * 256;
                int row = f >> 2, kq = (f & 3) << 2;
                Xs[kq + 0][row] = splitpack(xv[i].x); Xs[kq + 1][row] = splitpack(xv[i].y);
                Xs[kq + 2][row] = splitpack(xv[i].z); Xs[kq + 3][row] = splitpack(xv[i].w);
                Wsh[kq + 0][row] = splitpack(wv[i].x); Wsh[kq + 1][row] = splitpack(wv[i].y);
                Wsh[kq + 2][row] = splitpack(wv[i].z); Wsh[kq + 3][row] = splitpack(wv[i].w);
            }
            __syncthreads();
        }
    }

    // epilogue
#pragma unroll
    for (int mi = 0; mi < 4; mi++) {
#pragma unroll
        for (int half = 0; half < 2; half++) {
            int row = r0 + m0 + mi * 16 + half * 8 + g;
            if (row < R) {
#pragma unroll
                for (int nj = 0; nj < 4; nj++) {
                    int col = n0 + nj * 8 + t4 * 2;
                    float v0 = c[mi][nj][half * 2 + 0];
                    float v1 = c[mi][nj][half * 2 + 1];
                    if (bias) { v0 += bias[j0 + col]; v1 += bias[j0 + col + 1]; }
                    if (act) {
                        v0 = v0 > 0.f ? v0 : 0.01f * v0;
                        v1 = v1 > 0.f ? v1 : 0.01f * v1;
                    }
                    *(float2*)(Cbase + (size_t)row * D + col) = make_float2(v0, v1);
                }
            }
        }
    }
}

// g_M = A^T * B (A, B 1024x1024 row-major), fp32 SIMT (small share of total)
__global__ __launch_bounds__(256) void k_gemm128_tn(const float* __restrict__ A,
                                                    const float* __restrict__ B) {
    __shared__ float As[2][16][SPAD];
    __shared__ float Bs[2][16][SPAD];

    const int i0 = blockIdx.x * 128;
    const int j0 = blockIdx.y * 128;
    const int tid = threadIdx.x;
    const int tx = tid & 15, ty = tid >> 4;

    float acc[8][8];
#pragma unroll
    for (int r = 0; r < 8; r++)
#pragma unroll
        for (int c = 0; c < 8; c++) acc[r][c] = 0.f;

    float4 xs[2], ws[2];

#pragma unroll
    for (int i = 0; i < 2; i++) {
        int f = tid + i * 256;
        int i4 = (f & 31) << 2, kk = f >> 5;
        *(float4*)&As[0][kk][i4] = *(const float4*)(A + (size_t)kk * D4 + i0 + i4);
        *(float4*)&Bs[0][kk][i4] = *(const float4*)(B + (size_t)kk * D4 + j0 + i4);
    }
    __syncthreads();

    for (int kb = 0; kb < 64; kb++) {
        int cur = kb & 1, nxt = cur ^ 1;
        if (kb < 63) {
            int k0 = (kb + 1) * 16;
#pragma unroll
            for (int i = 0; i < 2; i++) {
                int f = tid + i * 256;
                int i4 = (f & 31) << 2, kk = f >> 5;
                xs[i] = *(const float4*)(A + (size_t)(k0 + kk) * D4 + i0 + i4);
                ws[i] = *(const float4*)(B + (size_t)(k0 + kk) * D4 + j0 + i4);
            }
        }
#pragma unroll
        for (int kk = 0; kk < 16; kk++) {
            float a[8], b[8];
            *(float4*)&a[0] = *(const float4*)&As[cur][kk][ty * 8];
            *(float4*)&a[4] = *(const float4*)&As[cur][kk][ty * 8 + 4];
            *(float4*)&b[0] = *(const float4*)&Bs[cur][kk][tx * 8];
            *(float4*)&b[4] = *(const float4*)&Bs[cur][kk][tx * 8 + 4];
#pragma unroll
            for (int r = 0; r < 8; r++)
#pragma unroll
                for (int c = 0; c < 8; c++) acc[r][c] += a[r] * b[c];
        }
        if (kb < 63) {
#pragma unroll
            for (int i = 0; i < 2; i++) {
                int f = tid + i * 256;
                int i4 = (f & 31) << 2, kk = f >> 5;
                *(float4*)&As[nxt][kk][i4] = xs[i];
                *(float4*)&Bs[nxt][kk][i4] = ws[i];
            }
            __syncthreads();
        }
    }

#pragma unroll
    for (int r = 0; r < 8; r++) {
        float* crow = g_M + (size_t)(i0 + ty * 8 + r) * D4 + j0 + tx * 8;
        *(float4*)crow = *(float4*)&acc[r][0];
        *(float4*)(crow + 4) = *(float4*)&acc[r][4];
    }
}

// edges are int32 rows of stride s32 (8 for int32 data, 16 for int64-as-int32; field f at f*fm)
__global__ void k_extract(const int* __restrict__ e1, const int* __restrict__ e0,
                          int s32, int fm) {
    int i = blockIdx.x * blockDim.x + threadIdx.x;
    if (i < E1C) {
        int q = e1[(size_t)i * s32 + 0 * fm];
        int s = e1[(size_t)i * s32 + 6 * fm];
        int d = e1[(size_t)i * s32 + 7 * fm];
        g_q1[i] = ((unsigned)q < NQ) ? q : 0;
        g_s1[i] = ((unsigned)s < N_NODES) ? s : 0;
        g_d1[i] = ((unsigned)d < N_NODES) ? d : 0;
    }
    if (i < E0C) {
        int q = e0[(size_t)i * s32 + 0 * fm];
        int s = e0[(size_t)i * s32 + 6 * fm];
        int d = e0[(size_t)i * s32 + 7 * fm];
        g_q0[i] = ((unsigned)q < NQ) ? q : 0;
        g_s0[i] = ((unsigned)s < N_NODES) ? s : 0;
        g_d0[i] = ((unsigned)d < N_NODES) ? d : 0;
    }
}

// per-query vectors from blocks of M = Wq^T Wk
__global__ void k_queryvec(const float* __restrict__ qst, const float* __restrict__ qr) {
    int q = blockIdx.x;
    int j = threadIdx.x;
    __shared__ float ss[256], tt[256], red[256];
    ss[j] = qst[q * D + j];
    tt[j] = qr[q * D + j];
    __syncthreads();
    int which = blockIdx.y;
    if (which == 0) {
        const float* row = g_M + (size_t)j * D4;
        float a = 0.f;
        for (int k = 0; k < D; k++) a += row[512 + k] * ss[k] + row[768 + k] * tt[k];
        g_v[q * D + j] = a;
    } else if (which == 1) {
        const float* row = g_M + (size_t)(256 + j) * D4;
        float a = 0.f;
        for (int k = 0; k < D; k++) a += row[512 + k] * ss[k] + row[768 + k] * tt[k];
        for (int k = 0; k < D; k++)
            a += g_M[(size_t)(512 + k) * D4 + 256 + j] * ss[k]
               + g_M[(size_t)(768 + k) * D4 + 256 + j] * tt[k];
        g_wz[q * D + j] = a;
    } else if (which == 2) {
        float a = 0.f;
        for (int k = 0; k < D; k++)
            a += g_M[(size_t)(512 + k) * D4 + j] * ss[k]
               + g_M[(size_t)(768 + k) * D4 + j] * tt[k];
        g_u[q * D + j] = a;
    } else {
        const float* rs = g_M + (size_t)(512 + j) * D4;
        const float* rt = g_M + (size_t)(768 + j) * D4;
        float ps = 0.f, pt = 0.f;
        for (int k = 0; k < D; k++) {
            ps += rs[512 + k] * ss[k] + rs[768 + k] * tt[k];
            pt += rt[512 + k] * ss[k] + rt[768 + k] * tt[k];
        }
        red[j] = ss[j] * ps + tt[j] * pt;
        __syncthreads();
        for (int s = 128; s; s >>= 1) {
            if (j < s) red[j] += red[j + s];
            __syncthreads();
        }
        if (j == 0) g_c[q] = red[0];
    }
}

// one warp per edge
__global__ void k_edge_score(int pass, int nrid, const float* __restrict__ nrext,
                             const float* __restrict__ rel, int ne) {
    int e = blockIdx.x * 8 + (threadIdx.x >> 5);
    if (e >= ne) return;
    int lane = threadIdx.x & 31;
    const int* qs = pass ? g_q1 : g_q0;
    const int* ssrc = pass ? g_s1 : g_s0;
    const int* sdst = pass ? g_d1 : g_d0;
    const float* NR = nrid ? dbuf(nrid) : nrext;
    int q = qs[e], s = ssrc[e], d = sdst[e];
    const float* ns = NR + (size_t)s * D;
    const float* nd = NR + (size_t)d * D;
    const float* re = rel + (size_t)e * D;
    const float* t1 = g_T1 + (size_t)d * D;
    const float* t2 = g_T2 + (size_t)d * D;
    const float* r1 = g_R1 + (size_t)e * D;
    const float* r2 = g_R2 + (size_t)e * D;
    const float* vq = g_v + q * D;
    const float* wq = g_wz + q * D;
    const float* uq = g_u + q * D;
    float a = 0.f;
#pragma unroll
    for (int i = 0; i < 8; i++) {
        int k = lane + 32 * i;
        a += ns[k] * (t1[k] + r1[k] + vq[k]);
        a += re[k] * (t2[k] + r2[k] + wq[k]);
        a += uq[k] * nd[k];
    }
#pragma unroll
    for (int o = 16; o; o >>= 1) a += __shfl_xor_sync(0xffffffffu, a, o);
    if (lane == 0) g_logits[e] = a + g_c[q];
}

__global__ void k_seg_init() {
    int i = blockIdx.x * blockDim.x + threadIdx.x;
    if (i < N_NODES) {
        g_segmax[i] = 0u;
        g_segsum[i] = 0.f;
        g_flag[i] = 0;
    }
}

__global__ void k_seg_max(int pass, int ne) {
    int i = blockIdx.x * blockDim.x + threadIdx.x;
    if (i < ne) {
        const int* seg = pass ? g_s1 : g_s0;
        atomicMax(&g_segmax[seg[i]], fenc(g_logits[i]));
    }
}

__global__ void k_seg_exp(int pass, int ne) {
    int i = blockIdx.x * blockDim.x + threadIdx.x;
    if (i < ne) {
        const int* seg = pass ? g_s1 : g_s0;
        float m = fdec(g_segmax[seg[i]]);
        float e = expf(g_logits[i] - m);
        g_exp[i] = e;
        atomicAdd(&g_segsum[seg[i]], e);
    }
}

__global__ void k_seg_div(int pass, const float* __restrict__ vscore, int ne) {
    int i = blockIdx.x * blockDim.x + threadIdx.x;
    if (i < ne) {
        const int* seg = pass ? g_s1 : g_s0;
        float sft = g_exp[i] / g_segsum[seg[i]];
        g_soft[i] = sft;
        if (vscore) g_target[i] = sft * vscore[seg[i]];
    }
}

// per-query bitonic sort of 256 (target, idx), descending value, ties by ascending idx
__global__ void k_topk(const int* __restrict__ edges1, int s32, int fm,
                       float* __restrict__ out_pe, float* __restrict__ out_oi) {
    int q = blockIdx.x;
    int t = threadIdx.x;
    __shared__ float sv[256];
    __shared__ int si[256];
    sv[t] = g_target[q * PG + t];
    si[t] = t;
    __syncthreads();
    for (int k = 2; k <= 256; k <<= 1) {
        for (int j = k >> 1; j > 0; j >>= 1) {
            int ixj = t ^ j;
            if (ixj > t) {
                float va = sv[t], vb = sv[ixj];
                int ia = si[t], ib = si[ixj];
                bool before = (va > vb) || (va == vb && ia < ib);
                bool up = ((t & k) == 0);
                if (up ? !before : before) {
                    sv[t] = vb; sv[ixj] = va;
                    si[t] = ib; si[ixj] = ia;
                }
            }
            __syncthreads();
        }
    }
    if (t < ME) {
        int oi = q * PG + si[t];
        int po = q * ME + t;
        out_oi[po] = (float)oi;
#pragma unroll
        for (int f = 0; f < 8; f++)
            out_pe[(size_t)po * 8 + f] = (float)edges1[(size_t)oi * s32 + f * fm];
        int s = edges1[(size_t)oi * s32 + 6 * fm];
        int d = edges1[(size_t)oi * s32 + 7 * fm];
        g_psrc[po] = ((unsigned)s < N_NODES) ? s : 0;
        g_pdst[po] = ((unsigned)d < N_NODES) ? d : 0;
        g_psoft[po] = g_soft[oi];
        g_ptgt[po] = sv[t];
    }
}

__global__ void k_zero_score(float* __restrict__ out_score) {
    int i = blockIdx.x * blockDim.x + threadIdx.x;
    if (i < N_NODES) out_score[i] = 0.f;
}

__global__ void k_scatter_score_flag(float* __restrict__ out_score) {
    int i = blockIdx.x * blockDim.x + threadIdx.x;
    if (i < NQ * ME) {
        atomicAdd(&out_score[g_pdst[i]], g_ptgt[i]);
        g_flag[g_psrc[i]] = 1;
    }
}

__global__ void k_set_flag0() {
    int i = blockIdx.x * blockDim.x + threadIdx.x;
    if (i < E0C) g_flag[g_s0[i]] = 1;
}

// mode 0: out = g_NR1, in = external NR ; mode 1: out = g_NR2, in = g_NR1
__global__ void k_scale_repr(int mode, const float* __restrict__ nrext) {
    size_t i = (size_t)blockIdx.x * blockDim.x + threadIdx.x;
    if (i < (size_t)N_NODES * (D / 4)) {
        const float4* in = mode ? (const float4*)g_NR1 : (const float4*)nrext;
        float4* out = mode ? (float4*)g_NR2 : (float4*)g_NR1;
        int n = (int)(i >> 6);
        float sc = g_flag[n] ? 0.2f : 1.0f;
        float4 vv = in[i];
        vv.x *= sc; vv.y *= sc; vv.z *= sc; vv.w *= sc;
        out[i] = vv;
    }
}

// mode 0: pruned edges, base external NR, acc g_NR1 ; mode 1: edges0, base g_NR1, acc g_NR2
__global__ void k_edge_agg(int mode, const float* __restrict__ nrext, int ne) {
    int e = blockIdx.x * 8 + (threadIdx.x >> 5);
    if (e >= ne) return;
    int lane = threadIdx.x & 31;
    const int* src = mode ? g_s0 : g_psrc;
    const int* dst = mode ? g_d0 : g_pdst;
    const float* w = mode ? g_soft : g_psoft;
    const float* base = mode ? g_NR1 : nrext;
    float* acc = mode ? g_NR2 : g_NR1;
    float cf = 0.8f * w[e];
    const float* bd = base + (size_t)dst[e] * D;
    float* as = acc + (size_t)src[e] * D;
#pragma unroll
    for (int i = 0; i < 8; i++) atomicAdd(as + lane + 32 * i, cf * bd[lane + 32 * i]);
}

// ---------------- host: kernel launches ONLY ----------------
extern "C" void kernel_launch(void* const* d_in, const int* in_sizes, int n_in,
                              void* d_out, int out_size) {
    int iVS = -1, iNR = -1, iE0 = -1, iE1 = -1, iR0 = -1, iR1 = -1;
    int iQA = -1, iQB = -1, iWA = -1, iWB = -1, iWL = -1, iBL = -1;
    for (int i = 0; i < n_in; i++) {
        long sz = in_sizes[i];
        if (sz == 50000) iVS = i;
        else if (sz == 12800000) iNR = i;
        else if (sz == 262144 || sz == 524288) { if (iE0 < 0) iE0 = i; else iE1 = i; }
        else if (sz == 8388608) { if (iR0 < 0) iR0 = i; else iR1 = i; }
        else if (sz == 32768) { if (iQA < 0) iQA = i; else iQB = i; }
        else if (sz == 1048576) { if (iWA < 0) iWA = i; else iWB = i; }
        else if (sz == 65536) iWL = i;
        else if (sz == 256) iBL = i;
    }
    bool dictOrder = (in_sizes[0] == 50000);

    const float* vscore = (const float*)d_in[iVS];
    const float* NR = (const float*)d_in[iNR];
    const int* e0 = (const int*)d_in[iE0];
    const int* e1 = (const int*)d_in[iE1];
    const float* rel0 = (const float*)d_in[iR0];
    const float* rel1 = (const float*)d_in[iR1];
    const float* qst = (const float*)d_in[dictOrder ? iQA : iQB];
    const float* qr = (const float*)d_in[dictOrder ? iQB : iQA];
    const float* Wq = (const float*)d_in[dictOrder ? iWA : iWB];
    const float* Wk = (const float*)d_in[dictOrder ? iWB : iWA];
    const float* Wl = (const float*)d_in[iWL];
    const float* bl = (const float*)d_in[iBL];

    int s32 = in_sizes[iE0] / 32768;
    int fm = s32 >> 3;

    float* out = (float*)d_out;
    float* out_score = out;
    float* out_repr = out + N_NODES;
    float* out_pe = out_repr + (size_t)N_NODES * D;
    float* out_oi = out_pe + (size_t)NQ * ME * 8;

    const int NB50K = (N_NODES + 255) / 256;
    const int GRN = (N_NODES + 127) / 128;   // 391
    const int GRE = E1C / 128;               // 256

    k_extract<<<128, 256>>>(e1, e0, s32, fm);
    k_gemm128_tn<<<dim3(8, 8), 256>>>(Wq, Wk);
    k_queryvec<<<dim3(NQ, 4), 256>>>(qst, qr);

    // ---- pass 1 tables: T1||T2 and R1||R2 fused (N=512 each), tensor-core split-tf32 ----
    k_gemm128t<<<dim3(GRN, 4), 256>>>(NR, 0, N_NODES, nullptr, 0, 0, nullptr, 0, nullptr, BUF_T1, BUF_T2);
    k_gemm128t<<<dim3(GRE, 4), 256>>>(rel1, 0, E1C, nullptr, 256, 0, nullptr, 0, nullptr, BUF_R1, BUF_R2);

    // ---- pass 1 scores + segment softmax ----
    k_seg_init<<<NB50K, 256>>>();
    k_edge_score<<<E1C / 8, 256>>>(1, 0, NR, rel1, E1C);
    k_seg_max<<<128, 256>>>(1, E1C);
    k_seg_exp<<<128, 256>>>(1, E1C);
    k_seg_div<<<128, 256>>>(1, vscore, E1C);

    // ---- top-64 per query ----
    k_topk<<<NQ, 256>>>(e1, s32, fm, out_pe, out_oi);

    // ---- updated node score + repr update 1 ----
    k_zero_score<<<NB50K, 256>>>(out_score);
    k_scatter_score_flag<<<(NQ * ME + 255) / 256, 256>>>(out_score);
    k_scale_repr<<<(N_NODES * (D / 4) + 255) / 256, 256>>>(0, NR);
    k_edge_agg<<<NQ * ME / 8, 256>>>(0, NR, NQ * ME);

    // ---- pass 2 tables ----
    k_gemm128t<<<dim3(GRN, 4), 256>>>(nullptr, BUF_NR1, N_NODES, nullptr, 0, 0, nullptr, 0, nullptr, BUF_T1, BUF_T2);
    k_gemm128t<<<dim3(GRE, 4), 256>>>(rel0, 0, E0C, nullptr, 256, 0, nullptr, 0, nullptr, BUF_R1, BUF_R2);

    // ---- pass 2 scores + softmax ----
    k_seg_init<<<NB50K, 256>>>();
    k_edge_score<<<E0C / 8, 256>>>(0, BUF_NR1, nullptr, rel0, E0C);
    k_seg_max<<<128, 256>>>(0, E0C);
    k_seg_exp<<<128, 256>>>(0, E0C);
    k_seg_div<<<128, 256>>>(0, nullptr, E0C);

    // ---- repr update 2 ----
    k_set_flag0<<<128, 256>>>();
    k_scale_repr<<<(N_NODES * (D / 4) + 255) / 256, 256>>>(1, nullptr);
    k_edge_agg<<<E0C / 8, 256>>>(1, nullptr, E0C);

    // ---- final linear layer + leaky relu (N=256 external out) ----
    k_gemm128t<<<dim3(GRN, 2), 256>>>(nullptr, BUF_NR2, N_NODES, Wl, -1, D, bl, 1, out_repr, 0, 0);
}

// round 11
// speedup vs baseline: 1.1802x; 1.1802x over previous
#include <cuda_runtime.h>
#include <math.h>

#define N_NODES 50000
#define D 256
#define D4 1024
#define NQ 128
#define PG 256
#define E1C 32768
#define E0C 32768
#define ME 64
#define SPAD 132
#define SP2 132

// ---------------- scratch (static device globals; referenced ONLY from device code) ----------------
__device__ __align__(16) float g_M[D4 * D4];   // Wq^T Wk
__device__ __align__(16) float g_v[NQ * D];
__device__ __align__(16) float g_wz[NQ * D];
__device__ __align__(16) float g_u[NQ * D];
__device__ float g_c[NQ];
__device__ __align__(16) float g_T1[N_NODES * D];
__device__ __align__(16) float g_T2[N_NODES * D];
__device__ __align__(16) float g_R1[E1C * D];
__device__ __align__(16) float g_R2[E1C * D];
__device__ float g_logits[E1C];
__device__ float g_exp[E1C];
__device__ float g_soft[E1C];
__device__ float g_target[E1C];
__device__ unsigned g_segmax[N_NODES];
__device__ float g_segsum[N_NODES];
__device__ int g_flag[N_NODES];
__device__ __align__(16) float g_NR1[N_NODES * D];
__device__ __align__(16) float g_NR2[N_NODES * D];
__device__ int g_s1[E1C], g_d1[E1C], g_q1[E1C];
__device__ int g_s0[E0C], g_d0[E0C], g_q0[E0C];
__device__ int g_psrc[NQ * ME], g_pdst[NQ * ME];
__device__ float g_psoft[NQ * ME], g_ptgt[NQ * ME];

#define BUF_T1 1
#define BUF_T2 2
#define BUF_R1 3
#define BUF_R2 4
#define BUF_NR1 5
#define BUF_NR2 6

__device__ __forceinline__ float* dbuf(int id) {
    switch (id) {
        case BUF_T1: return g_T1;
        case BUF_T2: return g_T2;
        case BUF_R1: return g_R1;
        case BUF_R2: return g_R2;
        case BUF_NR1: return g_NR1;
        default: return g_NR2;
    }
}

__device__ __forceinline__ unsigned fenc(float f) {
    unsigned u = __float_as_uint(f);
    return (u & 0x80000000u) ? ~u : (u | 0x80000000u);
}
__device__ __forceinline__ float fdec(unsigned e) {
    return __uint_as_float((e & 0x80000000u) ? (e ^ 0x80000000u) : ~e);
}

__device__ __forceinline__ unsigned f2tf32(float x) {
    unsigned r;
    asm("cvt.rna.tf32.f32 %0, %1;" : "=r"(r) : "f"(x));
    return r;
}

__device__ __forceinline__ void mma_tf32(float* c, unsigned a0, unsigned a1, unsigned a2,
                                         unsigned a3, unsigned b0, unsigned b1) {
    asm volatile(
        "mma.sync.aligned.m16n8k8.row.col.f32.tf32.tf32.f32 "
        "{%0,%1,%2,%3}, {%4,%5,%6,%7}, {%8,%9}, {%0,%1,%2,%3};"
        : "+f"(c[0]), "+f"(c[1]), "+f"(c[2]), "+f"(c[3])
        : "r"(a0), "r"(a1), "r"(a2), "r"(a3), "r"(b0), "r"(b1));
}

// hi/lo tf32 pair packed as float2 (x=hi bits, y=lo bits)
__device__ __forceinline__ float2 splitpack(float v) {
    unsigned h = f2tf32(v);
    unsigned l = f2tf32(v - __uint_as_float(h));
    return make_float2(__uint_as_float(h), __uint_as_float(l));
}

// ---------------- tensor-core split-tf32 GEMM ----------------
// C[R x N] = act( X[R x 256] @ W[N x 256]^T + bias ), fp32-accurate via hi/lo tf32 split.
// 128x128 block tile, 8 warps (2 m x 4 n of 64x32 warp tiles).
// K_BLK=8 double-buffered pipeline: prefetch+convert chunk kb+1 overlaps MMA on chunk kb,
// ONE barrier per chunk. Packed float2(hi,lo) smem -> one LDS.64 per fragment pair.
__global__ __launch_bounds__(256) void k_gemm128t(
    const float* __restrict__ xext, int xid, int R,
    const float* __restrict__ wext, long woff, int ldwext,
    const float* __restrict__ bias, int act,
    float* __restrict__ c1ext, int c1id, int c2id)
{
    const float* X = xid ? dbuf(xid) : xext;
    const float* W = (woff >= 0) ? (g_M + woff) : wext;
    const int ldw = (woff >= 0) ? D4 : ldwext;

    __shared__ float2 Xs[2][8][SP2];
    __shared__ float2 Wsh[2][8][SP2];

    const int r0 = blockIdx.x * 128;
    const int j0 = blockIdx.y * 128;
    float* Cbase;
    if (c1id == 0 && c2id == 0) Cbase = c1ext + j0;
    else Cbase = (j0 < 256) ? (dbuf(c1id) + j0) : (dbuf(c2id) + (j0 - 256));

    const int tid = threadIdx.x;
    const int wid = tid >> 5;
    const int lane = tid & 31;
    const int m0 = (wid >> 2) * 64;
    const int n0 = (wid & 3) * 32;
    const int g = lane >> 2;
    const int t4 = lane & 3;

    // G2S mapping: each thread owns one float4 (4 k-elems) of one row per matrix per chunk
    const int row = tid >> 1;          // 0..127
    const int kq = (tid & 1) << 2;     // 0 or 4
    const bool xok = (r0 + row) < R;
    const float* Xrow = X + (size_t)(r0 + row) * D + kq;
    const float* Wrow = W + (size_t)(j0 + row) * ldw + kq;

    float c[4][4][4];
#pragma unroll
    for (int mi = 0; mi < 4; mi++)
#pragma unroll
        for (int nj = 0; nj < 4; nj++)
#pragma unroll
            for (int k = 0; k < 4; k++) c[mi][nj][k] = 0.f;

    float4 xv = make_float4(0.f, 0.f, 0.f, 0.f), wv;

    // prime chunk 0
    if (xok) xv = *(const float4*)(Xrow);
    wv = *(const float4*)(Wrow);
    Xs[0][kq + 0][row] = splitpack(xv.x); Xs[0][kq + 1][row] = splitpack(xv.y);
    Xs[0][kq + 2][row] = splitpack(xv.z); Xs[0][kq + 3][row] = splitpack(xv.w);
    Wsh[0][kq + 0][row] = splitpack(wv.x); Wsh[0][kq + 1][row] = splitpack(wv.y);
    Wsh[0][kq + 2][row] = splitpack(wv.z); Wsh[0][kq + 3][row] = splitpack(wv.w);
    __syncthreads();

    for (int kb = 0; kb < 32; kb++) {
        const int cur = kb & 1, nxt = cur ^ 1;
        // prefetch next chunk from global
        if (kb < 31) {
            int k0 = (kb + 1) * 8;
            xv = make_float4(0.f, 0.f, 0.f, 0.f);
            if (xok) xv = *(const float4*)(Xrow + k0);
            wv = *(const float4*)(Wrow + k0);
        }
        // compute on current chunk (k = 0..7)
        {
            float2 b0[4], b1[4];
#pragma unroll
            for (int nj = 0; nj < 4; nj++) {
                int nc = n0 + nj * 8 + g;
                b0[nj] = Wsh[cur][t4][nc];
                b1[nj] = Wsh[cur][4 + t4][nc];
            }
#pragma unroll
            for (int mi = 0; mi < 4; mi++) {
                int mr = m0 + mi * 16;
                float2 a0 = Xs[cur][t4][mr + g];
                float2 a1 = Xs[cur][t4][mr + 8 + g];
                float2 a2 = Xs[cur][4 + t4][mr + g];
                float2 a3 = Xs[cur][4 + t4][mr + 8 + g];
                unsigned ah0 = __float_as_uint(a0.x), al0 = __float_as_uint(a0.y);
                unsigned ah1 = __float_as_uint(a1.x), al1 = __float_as_uint(a1.y);
                unsigned ah2 = __float_as_uint(a2.x), al2 = __float_as_uint(a2.y);
                unsigned ah3 = __float_as_uint(a3.x), al3 = __float_as_uint(a3.y);
#pragma unroll
                for (int nj = 0; nj < 4; nj++) {
                    unsigned bh0 = __float_as_uint(b0[nj].x), bl0 = __float_as_uint(b0[nj].y);
                    unsigned bh1 = __float_as_uint(b1[nj].x), bl1 = __float_as_uint(b1[nj].y);
                    mma_tf32(c[mi][nj], al0, al1, al2, al3, bh0, bh1);
                    mma_tf32(c[mi][nj], ah0, ah1, ah2, ah3, bl0, bl1);
                    mma_tf32(c[mi][nj], ah0, ah1, ah2, ah3, bh0, bh1);
                }
            }
        }
        // convert + store prefetched chunk into the other stage
        if (kb < 31) {
            Xs[nxt][kq + 0][row] = splitpack(xv.x); Xs[nxt][kq + 1][row] = splitpack(xv.y);
            Xs[nxt][kq + 2][row] = splitpack(xv.z); Xs[nxt][kq + 3][row] = splitpack(xv.w);
            Wsh[nxt][kq + 0][row] = splitpack(wv.x); Wsh[nxt][kq + 1][row] = splitpack(wv.y);
            Wsh[nxt][kq + 2][row] = splitpack(wv.z); Wsh[nxt][kq + 3][row] = splitpack(wv.w);
        }
        __syncthreads();
    }

    // epilogue
#pragma unroll
    for (int mi = 0; mi < 4; mi++) {
#pragma unroll
        for (int half = 0; half < 2; half++) {
            int orow = r0 + m0 + mi * 16 + half * 8 + g;
            if (orow < R) {
#pragma unroll
                for (int nj = 0; nj < 4; nj++) {
                    int col = n0 + nj * 8 + t4 * 2;
                    float v0 = c[mi][nj][half * 2 + 0];
                    float v1 = c[mi][nj][half * 2 + 1];
                    if (bias) { v0 += bias[j0 + col]; v1 += bias[j0 + col + 1]; }
                    if (act) {
                        v0 = v0 > 0.f ? v0 : 0.01f * v0;
                        v1 = v1 > 0.f ? v1 : 0.01f * v1;
                    }
                    *(float2*)(Cbase + (size_t)orow * D + col) = make_float2(v0, v1);
                }
            }
        }
    }
}

// g_M = A^T * B (A, B 1024x1024 row-major), fp32 SIMT (small share of total)
__global__ __launch_bounds__(256) void k_gemm128_tn(const float* __restrict__ A,
                                                    const float* __restrict__ B) {
    __shared__ float As[2][16][SPAD];
    __shared__ float Bs[2][16][SPAD];

    const int i0 = blockIdx.x * 128;
    const int j0 = blockIdx.y * 128;
    const int tid = threadIdx.x;
    const int tx = tid & 15, ty = tid >> 4;

    float acc[8][8];
#pragma unroll
    for (int r = 0; r < 8; r++)
#pragma unroll
        for (int c = 0; c < 8; c++) acc[r][c] = 0.f;

    float4 xs[2], ws[2];

#pragma unroll
    for (int i = 0; i < 2; i++) {
        int f = tid + i * 256;
        int i4 = (f & 31) << 2, kk = f >> 5;
        *(float4*)&As[0][kk][i4] = *(const float4*)(A + (size_t)kk * D4 + i0 + i4);
        *(float4*)&Bs[0][kk][i4] = *(const float4*)(B + (size_t)kk * D4 + j0 + i4);
    }
    __syncthreads();

    for (int kb = 0; kb < 64; kb++) {
        int cur = kb & 1, nxt = cur ^ 1;
        if (kb < 63) {
            int k0 = (kb + 1) * 16;
#pragma unroll
            for (int i = 0; i < 2; i++) {
                int f = tid + i * 256;
                int i4 = (f & 31) << 2, kk = f >> 5;
                xs[i] = *(const float4*)(A + (size_t)(k0 + kk) * D4 + i0 + i4);
                ws[i] = *(const float4*)(B + (size_t)(k0 + kk) * D4 + j0 + i4);
            }
        }
#pragma unroll
        for (int kk = 0; kk < 16; kk++) {
            float a[8], b[8];
            *(float4*)&a[0] = *(const float4*)&As[cur][kk][ty * 8];
            *(float4*)&a[4] = *(const float4*)&As[cur][kk][ty * 8 + 4];
            *(float4*)&b[0] = *(const float4*)&Bs[cur][kk][tx * 8];
            *(float4*)&b[4] = *(const float4*)&Bs[cur][kk][tx * 8 + 4];
#pragma unroll
            for (int r = 0; r < 8; r++)
#pragma unroll
                for (int c = 0; c < 8; c++) acc[r][c] += a[r] * b[c];
        }
        if (kb < 63) {
#pragma unroll
            for (int i = 0; i < 2; i++) {
                int f = tid + i * 256;
                int i4 = (f & 31) << 2, kk = f >> 5;
                *(float4*)&As[nxt][kk][i4] = xs[i];
                *(float4*)&Bs[nxt][kk][i4] = ws[i];
            }
            __syncthreads();
        }
    }

#pragma unroll
    for (int r = 0; r < 8; r++) {
        float* crow = g_M + (size_t)(i0 + ty * 8 + r) * D4 + j0 + tx * 8;
        *(float4*)crow = *(float4*)&acc[r][0];
        *(float4*)(crow + 4) = *(float4*)&acc[r][4];
    }
}

// edges are int32 rows of stride s32 (8 for int32 data, 16 for int64-as-int32; field f at f*fm)
__global__ void k_extract(const int* __restrict__ e1, const int* __restrict__ e0,
                          int s32, int fm) {
    int i = blockIdx.x * blockDim.x + threadIdx.x;
    if (i < E1C) {
        int q = e1[(size_t)i * s32 + 0 * fm];
        int s = e1[(size_t)i * s32 + 6 * fm];
        int d = e1[(size_t)i * s32 + 7 * fm];
        g_q1[i] = ((unsigned)q < NQ) ? q : 0;
        g_s1[i] = ((unsigned)s < N_NODES) ? s : 0;
        g_d1[i] = ((unsigned)d < N_NODES) ? d : 0;
    }
    if (i < E0C) {
        int q = e0[(size_t)i * s32 + 0 * fm];
        int s = e0[(size_t)i * s32 + 6 * fm];
        int d = e0[(size_t)i * s32 + 7 * fm];
        g_q0[i] = ((unsigned)q < NQ) ? q : 0;
        g_s0[i] = ((unsigned)s < N_NODES) ? s : 0;
        g_d0[i] = ((unsigned)d < N_NODES) ? d : 0;
    }
}

// per-query vectors from blocks of M = Wq^T Wk
__global__ void k_queryvec(const float* __restrict__ qst, const float* __restrict__ qr) {
    int q = blockIdx.x;
    int j = threadIdx.x;
    __shared__ float ss[256], tt[256], red[256];
    ss[j] = qst[q * D + j];
    tt[j] = qr[q * D + j];
    __syncthreads();
    int which = blockIdx.y;
    if (which == 0) {
        const float* row = g_M + (size_t)j * D4;
        float a = 0.f;
        for (int k = 0; k < D; k++) a += row[512 + k] * ss[k] + row[768 + k] * tt[k];
        g_v[q * D + j] = a;
    } else if (which == 1) {
        const float* row = g_M + (size_t)(256 + j) * D4;
        float a = 0.f;
        for (int k = 0; k < D; k++) a += row[512 + k] * ss[k] + row[768 + k] * tt[k];
        for (int k = 0; k < D; k++)
            a += g_M[(size_t)(512 + k) * D4 + 256 + j] * ss[k]
               + g_M[(size_t)(768 + k) * D4 + 256 + j] * tt[k];
        g_wz[q * D + j] = a;
    } else if (which == 2) {
        float a = 0.f;
        for (int k = 0; k < D; k++)
            a += g_M[(size_t)(512 + k) * D4 + j] * ss[k]
               + g_M[(size_t)(768 + k) * D4 + j] * tt[k];
        g_u[q * D + j] = a;
    } else {
        const float* rs = g_M + (size_t)(512 + j) * D4;
        const float* rt = g_M + (size_t)(768 + j) * D4;
        float ps = 0.f, pt = 0.f;
        for (int k = 0; k < D; k++) {
            ps += rs[512 + k] * ss[k] + rs[768 + k] * tt[k];
            pt += rt[512 + k] * ss[k] + rt[768 + k] * tt[k];
        }
        red[j] = ss[j] * ps + tt[j] * pt;
        __syncthreads();
        for (int s = 128; s; s >>= 1) {
            if (j < s) red[j] += red[j + s];
            __syncthreads();
        }
        if (j == 0) g_c[q] = red[0];
    }
}

// one warp per edge
__global__ void k_edge_score(int pass, int nrid, const float* __restrict__ nrext,
                             const float* __restrict__ rel, int ne) {
    int e = blockIdx.x * 8 + (threadIdx.x >> 5);
    if (e >= ne) return;
    int lane = threadIdx.x & 31;
    const int* qs = pass ? g_q1 : g_q0;
    const int* ssrc = pass ? g_s1 : g_s0;
    const int* sdst = pass ? g_d1 : g_d0;
    const float* NR = nrid ? dbuf(nrid) : nrext;
    int q = qs[e], s = ssrc[e], d = sdst[e];
    const float* ns = NR + (size_t)s * D;
    const float* nd = NR + (size_t)d * D;
    const float* re = rel + (size_t)e * D;
    const float* t1 = g_T1 + (size_t)d * D;
    const float* t2 = g_T2 + (size_t)d * D;
    const float* r1 = g_R1 + (size_t)e * D;
    const float* r2 = g_R2 + (size_t)e * D;
    const float* vq = g_v + q * D;
    const float* wq = g_wz + q * D;
    const float* uq = g_u + q * D;
    float a = 0.f;
#pragma unroll
    for (int i = 0; i < 8; i++) {
        int k = lane + 32 * i;
        a += ns[k] * (t1[k] + r1[k] + vq[k]);
        a += re[k] * (t2[k] + r2[k] + wq[k]);
        a += uq[k] * nd[k];
    }
#pragma unroll
    for (int o = 16; o; o >>= 1) a += __shfl_xor_sync(0xffffffffu, a, o);
    if (lane == 0) g_logits[e] = a + g_c[q];
}

__global__ void k_seg_init() {
    int i = blockIdx.x * blockDim.x + threadIdx.x;
    if (i < N_NODES) {
        g_segmax[i] = 0u;
        g_segsum[i] = 0.f;
        g_flag[i] = 0;
    }
}

__global__ void k_seg_max(int pass, int ne) {
    int i = blockIdx.x * blockDim.x + threadIdx.x;
    if (i < ne) {
        const int* seg = pass ? g_s1 : g_s0;
        atomicMax(&g_segmax[seg[i]], fenc(g_logits[i]));
    }
}

__global__ void k_seg_exp(int pass, int ne) {
    int i = blockIdx.x * blockDim.x + threadIdx.x;
    if (i < ne) {
        const int* seg = pass ? g_s1 : g_s0;
        float m = fdec(g_segmax[seg[i]]);
        float e = expf(g_logits[i] - m);
        g_exp[i] = e;
        atomicAdd(&g_segsum[seg[i]], e);
    }
}

__global__ void k_seg_div(int pass, const float* __restrict__ vscore, int ne) {
    int i = blockIdx.x * blockDim.x + threadIdx.x;
    if (i < ne) {
        const int* seg = pass ? g_s1 : g_s0;
        float sft = g_exp[i] / g_segsum[seg[i]];
        g_soft[i] = sft;
        if (vscore) g_target[i] = sft * vscore[seg[i]];
    }
}

// per-query bitonic sort of 256 (target, idx), descending value, ties by ascending idx
__global__ void k_topk(const int* __restrict__ edges1, int s32, int fm,
                       float* __restrict__ out_pe, float* __restrict__ out_oi) {
    int q = blockIdx.x;
    int t = threadIdx.x;
    __shared__ float sv[256];
    __shared__ int si[256];
    sv[t] = g_target[q * PG + t];
    si[t] = t;
    __syncthreads();
    for (int k = 2; k <= 256; k <<= 1) {
        for (int j = k >> 1; j > 0; j >>= 1) {
            int ixj = t ^ j;
            if (ixj > t) {
                float va = sv[t], vb = sv[ixj];
                int ia = si[t], ib = si[ixj];
                bool before = (va > vb) || (va == vb && ia < ib);
                bool up = ((t & k) == 0);
                if (up ? !before : before) {
                    sv[t] = vb; sv[ixj] = va;
                    si[t] = ib; si[ixj] = ia;
                }
            }
            __syncthreads();
        }
    }
    if (t < ME) {
        int oi = q * PG + si[t];
        int po = q * ME + t;
        out_oi[po] = (float)oi;
#pragma unroll
        for (int f = 0; f < 8; f++)
            out_pe[(size_t)po * 8 + f] = (float)edges1[(size_t)oi * s32 + f * fm];
        int s = edges1[(size_t)oi * s32 + 6 * fm];
        int d = edges1[(size_t)oi * s32 + 7 * fm];
        g_psrc[po] = ((unsigned)s < N_NODES) ? s : 0;
        g_pdst[po] = ((unsigned)d < N_NODES) ? d : 0;
        g_psoft[po] = g_soft[oi];
        g_ptgt[po] = sv[t];
    }
}

__global__ void k_zero_score(float* __restrict__ out_score) {
    int i = blockIdx.x * blockDim.x + threadIdx.x;
    if (i < N_NODES) out_score[i] = 0.f;
}

__global__ void k_scatter_score_flag(float* __restrict__ out_score) {
    int i = blockIdx.x * blockDim.x + threadIdx.x;
    if (i < NQ * ME) {
        atomicAdd(&out_score[g_pdst[i]], g_ptgt[i]);
        g_flag[g_psrc[i]] = 1;
    }
}

__global__ void k_set_flag0() {
    int i = blockIdx.x * blockDim.x + threadIdx.x;
    if (i < E0C) g_flag[g_s0[i]] = 1;
}

// mode 0: out = g_NR1, in = external NR ; mode 1: out = g_NR2, in = g_NR1
__global__ void k_scale_repr(int mode, const float* __restrict__ nrext) {
    size_t i = (size_t)blockIdx.x * blockDim.x + threadIdx.x;
    if (i < (size_t)N_NODES * (D / 4)) {
        const float4* in = mode ? (const float4*)g_NR1 : (const float4*)nrext;
        float4* out = mode ? (float4*)g_NR2 : (float4*)g_NR1;
        int n = (int)(i >> 6);
        float sc = g_flag[n] ? 0.2f : 1.0f;
        float4 vv = in[i];
        vv.x *= sc; vv.y *= sc; vv.z *= sc; vv.w *= sc;
        out[i] = vv;
    }
}

// mode 0: pruned edges, base external NR, acc g_NR1 ; mode 1: edges0, base g_NR1, acc g_NR2
__global__ void k_edge_agg(int mode, const float* __restrict__ nrext, int ne) {
    int e = blockIdx.x * 8 + (threadIdx.x >> 5);
    if (e >= ne) return;
    int lane = threadIdx.x & 31;
    const int* src = mode ? g_s0 : g_psrc;
    const int* dst = mode ? g_d0 : g_pdst;
    const float* w = mode ? g_soft : g_psoft;
    const float* base = mode ? g_NR1 : nrext;
    float* acc = mode ? g_NR2 : g_NR1;
    float cf = 0.8f * w[e];
    const float* bd = base + (size_t)dst[e] * D;
    float* as = acc + (size_t)src[e] * D;
#pragma unroll
    for (int i = 0; i < 8; i++) atomicAdd(as + lane + 32 * i, cf * bd[lane + 32 * i]);
}

// ---------------- host: kernel launches ONLY ----------------
extern "C" void kernel_launch(void* const* d_in, const int* in_sizes, int n_in,
                              void* d_out, int out_size) {
    int iVS = -1, iNR = -1, iE0 = -1, iE1 = -1, iR0 = -1, iR1 = -1;
    int iQA = -1, iQB = -1, iWA = -1, iWB = -1, iWL = -1, iBL = -1;
    for (int i = 0; i < n_in; i++) {
        long sz = in_sizes[i];
        if (sz == 50000) iVS = i;
        else if (sz == 12800000) iNR = i;
        else if (sz == 262144 || sz == 524288) { if (iE0 < 0) iE0 = i; else iE1 = i; }
        else if (sz == 8388608) { if (iR0 < 0) iR0 = i; else iR1 = i; }
        else if (sz == 32768) { if (iQA < 0) iQA = i; else iQB = i; }
        else if (sz == 1048576) { if (iWA < 0) iWA = i; else iWB = i; }
        else if (sz == 65536) iWL = i;
        else if (sz == 256) iBL = i;
    }
    bool dictOrder = (in_sizes[0] == 50000);

    const float* vscore = (const float*)d_in[iVS];
    const float* NR = (const float*)d_in[iNR];
    const int* e0 = (const int*)d_in[iE0];
    const int* e1 = (const int*)d_in[iE1];
    const float* rel0 = (const float*)d_in[iR0];
    const float* rel1 = (const float*)d_in[iR1];
    const float* qst = (const float*)d_in[dictOrder ? iQA : iQB];
    const float* qr = (const float*)d_in[dictOrder ? iQB : iQA];
    const float* Wq = (const float*)d_in[dictOrder ? iWA : iWB];
    const float* Wk = (const float*)d_in[dictOrder ? iWB : iWA];
    const float* Wl = (const float*)d_in[iWL];
    const float* bl = (const float*)d_in[iBL];

    int s32 = in_sizes[iE0] / 32768;
    int fm = s32 >> 3;

    float* out = (float*)d_out;
    float* out_score = out;
    float* out_repr = out + N_NODES;
    float* out_pe = out_repr + (size_t)N_NODES * D;
    float* out_oi = out_pe + (size_t)NQ * ME * 8;

    const int NB50K = (N_NODES + 255) / 256;
    const int GRN = (N_NODES + 127) / 128;   // 391
    const int GRE = E1C / 128;               // 256

    k_extract<<<128, 256>>>(e1, e0, s32, fm);
    k_gemm128_tn<<<dim3(8, 8), 256>>>(Wq, Wk);
    k_queryvec<<<dim3(NQ, 4), 256>>>(qst, qr);

    // ---- pass 1 tables: T1||T2 and R1||R2 fused (N=512 each), tensor-core split-tf32 ----
    k_gemm128t<<<dim3(GRN, 4), 256>>>(NR, 0, N_NODES, nullptr, 0, 0, nullptr, 0, nullptr, BUF_T1, BUF_T2);
    k_gemm128t<<<dim3(GRE, 4), 256>>>(rel1, 0, E1C, nullptr, 256, 0, nullptr, 0, nullptr, BUF_R1, BUF_R2);

    // ---- pass 1 scores + segment softmax ----
    k_seg_init<<<NB50K, 256>>>();
    k_edge_score<<<E1C / 8, 256>>>(1, 0, NR, rel1, E1C);
    k_seg_max<<<128, 256>>>(1, E1C);
    k_seg_exp<<<128, 256>>>(1, E1C);
    k_seg_div<<<128, 256>>>(1, vscore, E1C);

    // ---- top-64 per query ----
    k_topk<<<NQ, 256>>>(e1, s32, fm, out_pe, out_oi);

    // ---- updated node score + repr update 1 ----
    k_zero_score<<<NB50K, 256>>>(out_score);
    k_scatter_score_flag<<<(NQ * ME + 255) / 256, 256>>>(out_score);
    k_scale_repr<<<(N_NODES * (D / 4) + 255) / 256, 256>>>(0, NR);
    k_edge_agg<<<NQ * ME / 8, 256>>>(0, NR, NQ * ME);

    // ---- pass 2 tables ----
    k_gemm128t<<<dim3(GRN, 4), 256>>>(nullptr, BUF_NR1, N_NODES, nullptr, 0, 0, nullptr, 0, nullptr, BUF_T1, BUF_T2);
    k_gemm128t<<<dim3(GRE, 4), 256>>>(rel0, 0, E0C, nullptr, 256, 0, nullptr, 0, nullptr, BUF_R1, BUF_R2);

    // ---- pass 2 scores + softmax ----
    k_seg_init<<<NB50K, 256>>>();
    k_edge_score<<<E0C / 8, 256>>>(0, BUF_NR1, nullptr, rel0, E0C);
    k_seg_max<<<128, 256>>>(0, E0C);
    k_seg_exp<<<128, 256>>>(0, E0C);
    k_seg_div<<<128, 256>>>(0, nullptr, E0C);

    // ---- repr update 2 ----
    k_set_flag0<<<128, 256>>>();
    k_scale_repr<<<(N_NODES * (D / 4) + 255) / 256, 256>>>(1, nullptr);
    k_edge_agg<<<E0C / 8, 256>>>(1, nullptr, E0C);

    // ---- final linear layer + leaky relu (N=256 external out) ----
    k_gemm128t<<<dim3(GRN, 2), 256>>>(nullptr, BUF_NR2, N_NODES, Wl, -1, D, bl, 1, out_repr, 0, 0);
}

// round 13
// speedup vs baseline: 1.3842x; 1.1729x over previous
#include <cuda_runtime.h>
#include <math.h>

#define N_NODES 50000
#define D 256
#define D4 1024
#define NQ 128
#define PG 256
#define E1C 32768
#define E0C 32768
#define ME 64
#define SPAD 132
#define SP2 132

// ---------------- scratch (static device globals; referenced ONLY from device code) ----------------
__device__ __align__(16) float g_M[D4 * D4];   // Wq^T Wk
__device__ __align__(16) float g_v[NQ * D];
__device__ __align__(16) float g_wz[NQ * D];
__device__ __align__(16) float g_u[NQ * D];
__device__ float g_c[NQ];
__device__ __align__(16) float g_T1[N_NODES * D];
__device__ __align__(16) float g_T2[N_NODES * D];
__device__ __align__(16) float g_R1[E1C * D];
__device__ __align__(16) float g_R2[E1C * D];
__device__ float g_logits[E1C];
__device__ float g_exp[E1C];
__device__ float g_soft[E1C];
__device__ float g_target[E1C];
__device__ unsigned g_segmax[N_NODES];
__device__ float g_segsum[N_NODES];
__device__ int g_flag[N_NODES];
__device__ __align__(16) float g_NR1[N_NODES * D];
__device__ __align__(16) float g_NR2[N_NODES * D];
__device__ int g_s1[E1C], g_d1[E1C], g_q1[E1C];
__device__ int g_s0[E0C], g_d0[E0C], g_q0[E0C];
__device__ int g_psrc[NQ * ME], g_pdst[NQ * ME];
__device__ float g_psoft[NQ * ME], g_ptgt[NQ * ME];

// compaction of dst-node sets (tables only needed at dst rows)
__device__ int g_need1[N_NODES], g_need0[N_NODES];
__device__ int g_cid1[N_NODES], g_cid0[N_NODES];   // node -> compact row
__device__ int g_nl1[N_NODES], g_nl0[N_NODES];     // compact row -> node
__device__ int g_cnt1, g_cnt0;

// pre-split W operands: packed float2(hi,lo) per element, row-major [row][k]
__device__ __align__(16) float2 g_sWT[512 * D];   // M rows 0..511, cols 0..255
__device__ __align__(16) float2 g_sWR[512 * D];   // M rows 0..511, cols 256..511
__device__ __align__(16) float2 g_sWL[256 * D];   // Wl

#define BUF_T1 1
#define BUF_T2 2
#define BUF_R1 3
#define BUF_R2 4
#define BUF_NR1 5
#define BUF_NR2 6

__device__ __forceinline__ float* dbuf(int id) {
    switch (id) {
        case BUF_T1: return g_T1;
        case BUF_T2: return g_T2;
        case BUF_R1: return g_R1;
        case BUF_R2: return g_R2;
        case BUF_NR1: return g_NR1;
        default: return g_NR2;
    }
}

__device__ __forceinline__ unsigned fenc(float f) {
    unsigned u = __float_as_uint(f);
    return (u & 0x80000000u) ? ~u : (u | 0x80000000u);
}
__device__ __forceinline__ float fdec(unsigned e) {
    return __uint_as_float((e & 0x80000000u) ? (e ^ 0x80000000u) : ~e);
}

__device__ __forceinline__ unsigned f2tf32(float x) {
    unsigned r;
    asm("cvt.rna.tf32.f32 %0, %1;" : "=r"(r) : "f"(x));
    return r;
}

__device__ __forceinline__ void mma_tf32(float* c, unsigned a0, unsigned a1, unsigned a2,
                                         unsigned a3, unsigned b0, unsigned b1) {
    asm volatile(
        "mma.sync.aligned.m16n8k8.row.col.f32.tf32.tf32.f32 "
        "{%0,%1,%2,%3}, {%4,%5,%6,%7}, {%8,%9}, {%0,%1,%2,%3};"
        : "+f"(c[0]), "+f"(c[1]), "+f"(c[2]), "+f"(c[3])
        : "r"(a0), "r"(a1), "r"(a2), "r"(a3), "r"(b0), "r"(b1));
}

__device__ __forceinline__ float2 splitpack(float v) {
    unsigned h = f2tf32(v);
    unsigned l = f2tf32(v - __uint_as_float(h));
    return make_float2(__uint_as_float(h), __uint_as_float(l));
}

// ---------------- tensor-core split-tf32 GEMM ----------------
// C[R x N] = act( X @ W^T + bias ). W pre-split (wsel: 1=WT, 2=WR, 3=WL).
// Optional row gather (gsel: 1=(nl1,cnt1), 2=(nl0,cnt0)): X row i = Xfull[list[i]], R=cnt.
// 128x128 block tile, 8 warps, K_BLK=8 double-buffered pipeline, one barrier per chunk.
__global__ __launch_bounds__(256) void k_gemm128t(
    const float* __restrict__ xext, int xid, int R,
    int wsel,
    const float* __restrict__ bias, int act,
    float* __restrict__ c1ext, int c1id, int c2id,
    int gsel)
{
    const float* X = xid ? dbuf(xid) : xext;
    const float2* sW = (wsel == 1) ? g_sWT : (wsel == 2) ? g_sWR : g_sWL;
    const int* gather = (gsel == 1) ? g_nl1 : (gsel == 2) ? g_nl0 : nullptr;

    int Reff = R;
    if (gsel == 1) Reff = g_cnt1;
    else if (gsel == 2) Reff = g_cnt0;

    const int r0 = blockIdx.x * 128;
    if (r0 >= Reff) return;
    const int j0 = blockIdx.y * 128;

    __shared__ float2 Xs[2][8][SP2];
    __shared__ float2 Wsh[2][8][SP2];

    float* Cbase;
    if (c1id == 0 && c2id == 0) Cbase = c1ext + j0;
    else Cbase = (j0 < 256) ? (dbuf(c1id) + j0) : (dbuf(c2id) + (j0 - 256));

    const int tid = threadIdx.x;
    const int wid = tid >> 5;
    const int lane = tid & 31;
    const int m0 = (wid >> 2) * 64;
    const int n0 = (wid & 3) * 32;
    const int g = lane >> 2;
    const int t4 = lane & 3;

    // G2S mapping: each thread owns one float4-span (4 k-elems) of one row per matrix
    const int row = tid >> 1;          // 0..127
    const int kq = (tid & 1) << 2;     // 0 or 4
    const int lrow = r0 + row;
    const bool xok = lrow < Reff;
    int grow = lrow;
    if (gather && xok) grow = gather[lrow];
    const float* Xrow = X + (size_t)grow * D + kq;
    const float2* Wrow = sW + (size_t)(j0 + row) * D + kq;

    float c[4][4][4];
#pragma unroll
    for (int mi = 0; mi < 4; mi++)
#pragma unroll
        for (int nj = 0; nj < 4; nj++)
#pragma unroll
            for (int k = 0; k < 4; k++) c[mi][nj][k] = 0.f;

    float4 xv = make_float4(0.f, 0.f, 0.f, 0.f);
    float4 wa, wb;

    // prime chunk 0
    if (xok) xv = *(const float4*)(Xrow);
    wa = ((const float4*)Wrow)[0];
    wb = ((const float4*)Wrow)[1];
    Xs[0][kq + 0][row] = splitpack(xv.x); Xs[0][kq + 1][row] = splitpack(xv.y);
    Xs[0][kq + 2][row] = splitpack(xv.z); Xs[0][kq + 3][row] = splitpack(xv.w);
    Wsh[0][kq + 0][row] = make_float2(wa.x, wa.y);
    Wsh[0][kq + 1][row] = make_float2(wa.z, wa.w);
    Wsh[0][kq + 2][row] = make_float2(wb.x, wb.y);
    Wsh[0][kq + 3][row] = make_float2(wb.z, wb.w);
    __syncthreads();

    for (int kb = 0; kb < 32; kb++) {
        const int cur = kb & 1, nxt = cur ^ 1;
        if (kb < 31) {
            int k0 = (kb + 1) * 8;
            xv = make_float4(0.f, 0.f, 0.f, 0.f);
            if (xok) xv = *(const float4*)(Xrow + k0);
            wa = ((const float4*)(Wrow + k0))[0];
            wb = ((const float4*)(Wrow + k0))[1];
        }
        {
            float2 b0[4], b1[4];
#pragma unroll
            for (int nj = 0; nj < 4; nj++) {
                int nc = n0 + nj * 8 + g;
                b0[nj] = Wsh[cur][t4][nc];
                b1[nj] = Wsh[cur][4 + t4][nc];
            }
#pragma unroll
            for (int mi = 0; mi < 4; mi++) {
                int mr = m0 + mi * 16;
                float2 a0 = Xs[cur][t4][mr + g];
                float2 a1 = Xs[cur][t4][mr + 8 + g];
                float2 a2 = Xs[cur][4 + t4][mr + g];
                float2 a3 = Xs[cur][4 + t4][mr + 8 + g];
                unsigned ah0 = __float_as_uint(a0.x), al0 = __float_as_uint(a0.y);
                unsigned ah1 = __float_as_uint(a1.x), al1 = __float_as_uint(a1.y);
                unsigned ah2 = __float_as_uint(a2.x), al2 = __float_as_uint(a2.y);
                unsigned ah3 = __float_as_uint(a3.x), al3 = __float_as_uint(a3.y);
#pragma unroll
                for (int nj = 0; nj < 4; nj++) {
                    unsigned bh0 = __float_as_uint(b0[nj].x), bl0 = __float_as_uint(b0[nj].y);
                    unsigned bh1 = __float_as_uint(b1[nj].x), bl1 = __float_as_uint(b1[nj].y);
                    mma_tf32(c[mi][nj], al0, al1, al2, al3, bh0, bh1);
                    mma_tf32(c[mi][nj], ah0, ah1, ah2, ah3, bl0, bl1);
                    mma_tf32(c[mi][nj], ah0, ah1, ah2, ah3, bh0, bh1);
                }
            }
        }
        if (kb < 31) {
            Xs[nxt][kq + 0][row] = splitpack(xv.x); Xs[nxt][kq + 1][row] = splitpack(xv.y);
            Xs[nxt][kq + 2][row] = splitpack(xv.z); Xs[nxt][kq + 3][row] = splitpack(xv.w);
            Wsh[nxt][kq + 0][row] = make_float2(wa.x, wa.y);
            Wsh[nxt][kq + 1][row] = make_float2(wa.z, wa.w);
            Wsh[nxt][kq + 2][row] = make_float2(wb.x, wb.y);
            Wsh[nxt][kq + 3][row] = make_float2(wb.z, wb.w);
        }
        __syncthreads();
    }

    // epilogue
#pragma unroll
    for (int mi = 0; mi < 4; mi++) {
#pragma unroll
        for (int half = 0; half < 2; half++) {
            int orow = r0 + m0 + mi * 16 + half * 8 + g;
            if (orow < Reff) {
#pragma unroll
                for (int nj = 0; nj < 4; nj++) {
                    int col = n0 + nj * 8 + t4 * 2;
                    float v0 = c[mi][nj][half * 2 + 0];
                    float v1 = c[mi][nj][half * 2 + 1];
                    if (bias) { v0 += bias[j0 + col]; v1 += bias[j0 + col + 1]; }
                    if (act) {
                        v0 = v0 > 0.f ? v0 : 0.01f * v0;
                        v1 = v1 > 0.f ? v1 : 0.01f * v1;
                    }
                    *(float2*)(Cbase + (size_t)orow * D + col) = make_float2(v0, v1);
                }
            }
        }
    }
}

// g_M = A^T * B (A, B 1024x1024 row-major), fp32 SIMT (small share of total)
__global__ __launch_bounds__(256) void k_gemm128_tn(const float* __restrict__ A,
                                                    const float* __restrict__ B) {
    __shared__ float As[2][16][SPAD];
    __shared__ float Bs[2][16][SPAD];

    const int i0 = blockIdx.x * 128;
    const int j0 = blockIdx.y * 128;
    const int tid = threadIdx.x;
    const int tx = tid & 15, ty = tid >> 4;

    float acc[8][8];
#pragma unroll
    for (int r = 0; r < 8; r++)
#pragma unroll
        for (int c = 0; c < 8; c++) acc[r][c] = 0.f;

    float4 xs[2], ws[2];

#pragma unroll
    for (int i = 0; i < 2; i++) {
        int f = tid + i * 256;
        int i4 = (f & 31) << 2, kk = f >> 5;
        *(float4*)&As[0][kk][i4] = *(const float4*)(A + (size_t)kk * D4 + i0 + i4);
        *(float4*)&Bs[0][kk][i4] = *(const float4*)(B + (size_t)kk * D4 + j0 + i4);
    }
    __syncthreads();

    for (int kb = 0; kb < 64; kb++) {
        int cur = kb & 1, nxt = cur ^ 1;
        if (kb < 63) {
            int k0 = (kb + 1) * 16;
#pragma unroll
            for (int i = 0; i < 2; i++) {
                int f = tid + i * 256;
                int i4 = (f & 31) << 2, kk = f >> 5;
                xs[i] = *(const float4*)(A + (size_t)(k0 + kk) * D4 + i0 + i4);
                ws[i] = *(const float4*)(B + (size_t)(k0 + kk) * D4 + j0 + i4);
            }
        }
#pragma unroll
        for (int kk = 0; kk < 16; kk++) {
            float a[8], b[8];
            *(float4*)&a[0] = *(const float4*)&As[cur][kk][ty * 8];
            *(float4*)&a[4] = *(const float4*)&As[cur][kk][ty * 8 + 4];
            *(float4*)&b[0] = *(const float4*)&Bs[cur][kk][tx * 8];
            *(float4*)&b[4] = *(const float4*)&Bs[cur][kk][tx * 8 + 4];
#pragma unroll
            for (int r = 0; r < 8; r++)
#pragma unroll
                for (int c = 0; c < 8; c++) acc[r][c] += a[r] * b[c];
        }
        if (kb < 63) {
#pragma unroll
            for (int i = 0; i < 2; i++) {
                int f = tid + i * 256;
                int i4 = (f & 31) << 2, kk = f >> 5;
                *(float4*)&As[nxt][kk][i4] = xs[i];
                *(float4*)&Bs[nxt][kk][i4] = ws[i];
            }
            __syncthreads();
        }
    }

#pragma unroll
    for (int r = 0; r < 8; r++) {
        float* crow = g_M + (size_t)(i0 + ty * 8 + r) * D4 + j0 + tx * 8;
        *(float4*)crow = *(float4*)&acc[r][0];
        *(float4*)(crow + 4) = *(float4*)&acc[r][4];
    }
}

// pre-split W into packed float2(hi,lo). mode 1: WT from g_M[.][0:256];
// mode 2: WR from g_M[.][256:512]; mode 3: WL from ext (256x256 row-major).
__global__ void k_splitw(const float* __restrict__ ext, int mode) {
    int i = blockIdx.x * blockDim.x + threadIdx.x;
    int total = (mode == 3 ? 256 : 512) * D;
    if (i >= total) return;
    int r = i >> 8, cidx = i & 255;
    float v;
    if (mode == 1) v = g_M[(size_t)r * D4 + cidx];
    else if (mode == 2) v = g_M[(size_t)r * D4 + 256 + cidx];
    else v = ext[i];
    float2 p = splitpack(v);
    if (mode == 1) g_sWT[i] = p;
    else if (mode == 2) g_sWR[i] = p;
    else g_sWL[i] = p;
}

// edges are int32 rows of stride s32 (8 for int32 data, 16 for int64-as-int32; field f at f*fm)
__global__ void k_extract(const int* __restrict__ e1, const int* __restrict__ e0,
                          int s32, int fm) {
    int i = blockIdx.x * blockDim.x + threadIdx.x;
    if (i < E1C) {
        int q = e1[(size_t)i * s32 + 0 * fm];
        int s = e1[(size_t)i * s32 + 6 * fm];
        int d = e1[(size_t)i * s32 + 7 * fm];
        g_q1[i] = ((unsigned)q < NQ) ? q : 0;
        g_s1[i] = ((unsigned)s < N_NODES) ? s : 0;
        g_d1[i] = ((unsigned)d < N_NODES) ? d : 0;
    }
    if (i < E0C) {
        int q = e0[(size_t)i * s32 + 0 * fm];
        int s = e0[(size_t)i * s32 + 6 * fm];
        int d = e0[(size_t)i * s32 + 7 * fm];
        g_q0[i] = ((unsigned)q < NQ) ? q : 0;
        g_s0[i] = ((unsigned)s < N_NODES) ? s : 0;
        g_d0[i] = ((unsigned)d < N_NODES) ? d : 0;
    }
}

// dst-set compaction: init, mark, compact (atomic order is nondeterministic but
// outputs are invariant — tables are written at cid[n] and read at cid[n]).
__global__ void k_markinit() {
    int i = blockIdx.x * blockDim.x + threadIdx.x;
    if (i < N_NODES) { g_need1[i] = 0; g_need0[i] = 0; }
    if (i == 0) { g_cnt1 = 0; g_cnt0 = 0; }
}
__global__ void k_mark() {
    int i = blockIdx.x * blockDim.x + threadIdx.x;
    if (i < E1C) g_need1[g_d1[i]] = 1;
    if (i < E0C) g_need0[g_d0[i]] = 1;
}
__global__ void k_compact() {
    int i = blockIdx.x * blockDim.x + threadIdx.x;
    if (i < N_NODES) {
        if (g_need1[i]) { int p = atomicAdd(&g_cnt1, 1); g_cid1[i] = p; g_nl1[p] = i; }
        if (g_need0[i]) { int p = atomicAdd(&g_cnt0, 1); g_cid0[i] = p; g_nl0[p] = i; }
    }
}

// per-query vectors from blocks of M = Wq^T Wk
__global__ void k_queryvec(const float* __restrict__ qst, const float* __restrict__ qr) {
    int q = blockIdx.x;
    int j = threadIdx.x;
    __shared__ float ss[256], tt[256], red[256];
    ss[j] = qst[q * D + j];
    tt[j] = qr[q * D + j];
    __syncthreads();
    int which = blockIdx.y;
    if (which == 0) {
        const float* row = g_M + (size_t)j * D4;
        float a = 0.f;
        for (int k = 0; k < D; k++) a += row[512 + k] * ss[k] + row[768 + k] * tt[k];
        g_v[q * D + j] = a;
    } else if (which == 1) {
        const float* row = g_M + (size_t)(256 + j) * D4;
        float a = 0.f;
        for (int k = 0; k < D; k++) a += row[512 + k] * ss[k] + row[768 + k] * tt[k];
        for (int k = 0; k < D; k++)
            a += g_M[(size_t)(512 + k) * D4 + 256 + j] * ss[k]
               + g_M[(size_t)(768 + k) * D4 + 256 + j] * tt[k];
        g_wz[q * D + j] = a;
    } else if (which == 2) {
        float a = 0.f;
        for (int k = 0; k < D; k++)
            a += g_M[(size_t)(512 + k) * D4 + j] * ss[k]
               + g_M[(size_t)(768 + k) * D4 + j] * tt[k];
        g_u[q * D + j] = a;
    } else {
        const float* rs = g_M + (size_t)(512 + j) * D4;
        const float* rt = g_M + (size_t)(768 + j) * D4;
        float ps = 0.f, pt = 0.f;
        for (int k = 0; k < D; k++) {
            ps += rs[512 + k] * ss[k] + rs[768 + k] * tt[k];
            pt += rt[512 + k] * ss[k] + rt[768 + k] * tt[k];
        }
        red[j] = ss[j] * ps + tt[j] * pt;
        __syncthreads();
        for (int s = 128; s; s >>= 1) {
            if (j < s) red[j] += red[j + s];
            __syncthreads();
        }
        if (j == 0) g_c[q] = red[0];
    }
}

// one warp per edge; T tables indexed through the pass's compact id map
__global__ void k_edge_score(int pass, int nrid, const float* __restrict__ nrext,
                             const float* __restrict__ rel, int ne) {
    int e = blockIdx.x * 8 + (threadIdx.x >> 5);
    if (e >= ne) return;
    int lane = threadIdx.x & 31;
    const int* qs = pass ? g_q1 : g_q0;
    const int* ssrc = pass ? g_s1 : g_s0;
    const int* sdst = pass ? g_d1 : g_d0;
    const int* cid = pass ? g_cid1 : g_cid0;
    const float* NR = nrid ? dbuf(nrid) : nrext;
    int q = qs[e], s = ssrc[e], d = sdst[e];
    int cd = cid[d];
    const float* ns = NR + (size_t)s * D;
    const float* nd = NR + (size_t)d * D;
    const float* re = rel + (size_t)e * D;
    const float* t1 = g_T1 + (size_t)cd * D;
    const float* t2 = g_T2 + (size_t)cd * D;
    const float* r1 = g_R1 + (size_t)e * D;
    const float* r2 = g_R2 + (size_t)e * D;
    const float* vq = g_v + q * D;
    const float* wq = g_wz + q * D;
    const float* uq = g_u + q * D;
    float a = 0.f;
#pragma unroll
    for (int i = 0; i < 8; i++) {
        int k = lane + 32 * i;
        a += ns[k] * (t1[k] + r1[k] + vq[k]);
        a += re[k] * (t2[k] + r2[k] + wq[k]);
        a += uq[k] * nd[k];
    }
#pragma unroll
    for (int o = 16; o; o >>= 1) a += __shfl_xor_sync(0xffffffffu, a, o);
    if (lane == 0) g_logits[e] = a + g_c[q];
}

__global__ void k_seg_init() {
    int i = blockIdx.x * blockDim.x + threadIdx.x;
    if (i < N_NODES) {
        g_segmax[i] = 0u;
        g_segsum[i] = 0.f;
        g_flag[i] = 0;
    }
}

__global__ void k_seg_max(int pass, int ne) {
    int i = blockIdx.x * blockDim.x + threadIdx.x;
    if (i < ne) {
        const int* seg = pass ? g_s1 : g_s0;
        atomicMax(&g_segmax[seg[i]], fenc(g_logits[i]));
    }
}

__global__ void k_seg_exp(int pass, int ne) {
    int i = blockIdx.x * blockDim.x + threadIdx.x;
    if (i < ne) {
        const int* seg = pass ? g_s1 : g_s0;
        float m = fdec(g_segmax[seg[i]]);
        float e = expf(g_logits[i] - m);
        g_exp[i] = e;
        atomicAdd(&g_segsum[seg[i]], e);
    }
}

__global__ void k_seg_div(int pass, const float* __restrict__ vscore, int ne) {
    int i = blockIdx.x * blockDim.x + threadIdx.x;
    if (i < ne) {
        const int* seg = pass ? g_s1 : g_s0;
        float sft = g_exp[i] / g_segsum[seg[i]];
        g_soft[i] = sft;
        if (vscore) g_target[i] = sft * vscore[seg[i]];
    }
}

// per-query bitonic sort of 256 (target, idx), descending value, ties by ascending idx
__global__ void k_topk(const int* __restrict__ edges1, int s32, int fm,
                       float* __restrict__ out_pe, float* __restrict__ out_oi) {
    int q = blockIdx.x;
    int t = threadIdx.x;
    __shared__ float sv[256];
    __shared__ int si[256];
    sv[t] = g_target[q * PG + t];
    si[t] = t;
    __syncthreads();
    for (int k = 2; k <= 256; k <<= 1) {
        for (int j = k >> 1; j > 0; j >>= 1) {
            int ixj = t ^ j;
            if (ixj > t) {
                float va = sv[t], vb = sv[ixj];
                int ia = si[t], ib = si[ixj];
                bool before = (va > vb) || (va == vb && ia < ib);
                bool up = ((t & k) == 0);
                if (up ? !before : before) {
                    sv[t] = vb; sv[ixj] = va;
                    si[t] = ib; si[ixj] = ia;
                }
            }
            __syncthreads();
        }
    }
    if (t < ME) {
        int oi = q * PG + si[t];
        int po = q * ME + t;
        out_oi[po] = (float)oi;
#pragma unroll
        for (int f = 0; f < 8; f++)
            out_pe[(size_t)po * 8 + f] = (float)edges1[(size_t)oi * s32 + f * fm];
        int s = edges1[(size_t)oi * s32 + 6 * fm];
        int d = edges1[(size_t)oi * s32 + 7 * fm];
        g_psrc[po] = ((unsigned)s < N_NODES) ? s : 0;
        g_pdst[po] = ((unsigned)d < N_NODES) ? d : 0;
        g_psoft[po] = g_soft[oi];
        g_ptgt[po] = sv[t];
    }
}

__global__ void k_zero_score(float* __restrict__ out_score) {
    int i = blockIdx.x * blockDim.x + threadIdx.x;
    if (i < N_NODES) out_score[i] = 0.f;
}

__global__ void k_scatter_score_flag(float* __restrict__ out_score) {
    int i = blockIdx.x * blockDim.x + threadIdx.x;
    if (i < NQ * ME) {
        atomicAdd(&out_score[g_pdst[i]], g_ptgt[i]);
        g_flag[g_psrc[i]] = 1;
    }
}

__global__ void k_set_flag0() {
    int i = blockIdx.x * blockDim.x + threadIdx.x;
    if (i < E0C) g_flag[g_s0[i]] = 1;
}

// mode 0: out = g_NR1, in = external NR ; mode 1: out = g_NR2, in = g_NR1
__global__ void k_scale_repr(int mode, const float* __restrict__ nrext) {
    size_t i = (size_t)blockIdx.x * blockDim.x + threadIdx.x;
    if (i < (size_t)N_NODES * (D / 4)) {
        const float4* in = mode ? (const float4*)g_NR1 : (const float4*)nrext;
        float4* out = mode ? (float4*)g_NR2 : (float4*)g_NR1;
        int n = (int)(i >> 6);
        float sc = g_flag[n] ? 0.2f : 1.0f;
        float4 vv = in[i];
        vv.x *= sc; vv.y *= sc; vv.z *= sc; vv.w *= sc;
        out[i] = vv;
    }
}

// mode 0: pruned edges, base external NR, acc g_NR1 ; mode 1: edges0, base g_NR1, acc g_NR2
__global__ void k_edge_agg(int mode, const float* __restrict__ nrext, int ne) {
    int e = blockIdx.x * 8 + (threadIdx.x >> 5);
    if (e >= ne) return;
    int lane = threadIdx.x & 31;
    const int* src = mode ? g_s0 : g_psrc;
    const int* dst = mode ? g_d0 : g_pdst;
    const float* w = mode ? g_soft : g_psoft;
    const float* base = mode ? g_NR1 : nrext;
    float* acc = mode ? g_NR2 : g_NR1;
    float cf = 0.8f * w[e];
    const float* bd = base + (size_t)dst[e] * D;
    float* as = acc + (size_t)src[e] * D;
#pragma unroll
    for (int i = 0; i < 8; i++) atomicAdd(as + lane + 32 * i, cf * bd[lane + 32 * i]);
}

// ---------------- host: kernel launches ONLY ----------------
extern "C" void kernel_launch(void* const* d_in, const int* in_sizes, int n_in,
                              void* d_out, int out_size) {
    int iVS = -1, iNR = -1, iE0 = -1, iE1 = -1, iR0 = -1, iR1 = -1;
    int iQA = -1, iQB = -1, iWA = -1, iWB = -1, iWL = -1, iBL = -1;
    for (int i = 0; i < n_in; i++) {
        long sz = in_sizes[i];
        if (sz == 50000) iVS = i;
        else if (sz == 12800000) iNR = i;
        else if (sz == 262144 || sz == 524288) { if (iE0 < 0) iE0 = i; else iE1 = i; }
        else if (sz == 8388608) { if (iR0 < 0) iR0 = i; else iR1 = i; }
        else if (sz == 32768) { if (iQA < 0) iQA = i; else iQB = i; }
        else if (sz == 1048576) { if (iWA < 0) iWA = i; else iWB = i; }
        else if (sz == 65536) iWL = i;
        else if (sz == 256) iBL = i;
    }
    bool dictOrder = (in_sizes[0] == 50000);

    const float* vscore = (const float*)d_in[iVS];
    const float* NR = (const float*)d_in[iNR];
    const int* e0 = (const int*)d_in[iE0];
    const int* e1 = (const int*)d_in[iE1];
    const float* rel0 = (const float*)d_in[iR0];
    const float* rel1 = (const float*)d_in[iR1];
    const float* qst = (const float*)d_in[dictOrder ? iQA : iQB];
    const float* qr = (const float*)d_in[dictOrder ? iQB : iQA];
    const float* Wq = (const float*)d_in[dictOrder ? iWA : iWB];
    const float* Wk = (const float*)d_in[dictOrder ? iWB : iWA];
    const float* Wl = (const float*)d_in[iWL];
    const float* bl = (const float*)d_in[iBL];

    int s32 = in_sizes[iE0] / 32768;
    int fm = s32 >> 3;

    float* out = (float*)d_out;
    float* out_score = out;
    float* out_repr = out + N_NODES;
    float* out_pe = out_repr + (size_t)N_NODES * D;
    float* out_oi = out_pe + (size_t)NQ * ME * 8;

    const int NB50K = (N_NODES + 255) / 256;
    const int GRN = (N_NODES + 127) / 128;   // 391
    const int GRE = E1C / 128;               // 256

    k_extract<<<128, 256>>>(e1, e0, s32, fm);
    k_markinit<<<NB50K, 256>>>();
    k_mark<<<128, 256>>>();
    k_compact<<<NB50K, 256>>>();
    k_gemm128_tn<<<dim3(8, 8), 256>>>(Wq, Wk);
    k_splitw<<<512, 256>>>(nullptr, 1);
    k_splitw<<<512, 256>>>(nullptr, 2);
    k_splitw<<<256, 256>>>(Wl, 3);
    k_queryvec<<<dim3(NQ, 4), 256>>>(qst, qr);

    // ---- pass 1 tables: T (compacted dst1 rows) and R (all edges), split-tf32 ----
    k_gemm128t<<<dim3(GRN, 4), 256>>>(NR, 0, N_NODES, 1, nullptr, 0, nullptr, BUF_T1, BUF_T2, 1);
    k_gemm128t<<<dim3(GRE, 4), 256>>>(rel1, 0, E1C, 2, nullptr, 0, nullptr, BUF_R1, BUF_R2, 0);

    // ---- pass 1 scores + segment softmax ----
    k_seg_init<<<NB50K, 256>>>();
    k_edge_score<<<E1C / 8, 256>>>(1, 0, NR, rel1, E1C);
    k_seg_max<<<128, 256>>>(1, E1C);
    k_seg_exp<<<128, 256>>>(1, E1C);
    k_seg_div<<<128, 256>>>(1, vscore, E1C);

    // ---- top-64 per query ----
    k_topk<<<NQ, 256>>>(e1, s32, fm, out_pe, out_oi);

    // ---- updated node score + repr update 1 ----
    k_zero_score<<<NB50K, 256>>>(out_score);
    k_scatter_score_flag<<<(NQ * ME + 255) / 256, 256>>>(out_score);
    k_scale_repr<<<(N_NODES * (D / 4) + 255) / 256, 256>>>(0, NR);
    k_edge_agg<<<NQ * ME / 8, 256>>>(0, NR, NQ * ME);

    // ---- pass 2 tables (compacted dst0 rows) ----
    k_gemm128t<<<dim3(GRN, 4), 256>>>(nullptr, BUF_NR1, N_NODES, 1, nullptr, 0, nullptr, BUF_T1, BUF_T2, 2);
    k_gemm128t<<<dim3(GRE, 4), 256>>>(rel0, 0, E0C, 2, nullptr, 0, nullptr, BUF_R1, BUF_R2, 0);

    // ---- pass 2 scores + softmax ----
    k_seg_init<<<NB50K, 256>>>();
    k_edge_score<<<E0C / 8, 256>>>(0, BUF_NR1, nullptr, rel0, E0C);
    k_seg_max<<<128, 256>>>(0, E0C);
    k_seg_exp<<<128, 256>>>(0, E0C);
    k_seg_div<<<128, 256>>>(0, nullptr, E0C);

    // ---- repr update 2 ----
    k_set_flag0<<<128, 256>>>();
    k_scale_repr<<<(N_NODES * (D / 4) + 255) / 256, 256>>>(1, nullptr);
    k_edge_agg<<<E0C / 8, 256>>>(1, nullptr, E0C);

    // ---- final linear layer + leaky relu (N=256 external out, full node set) ----
    k_gemm128t<<<dim3(GRN, 2), 256>>>(nullptr, BUF_NR2, N_NODES, 3, bl, 1, out_repr, 0, 0, 0);
}